// round 1
// baseline (speedup 1.0000x reference)
#include <cuda_runtime.h>

#define BATCH 2
#define SEQ 2048
#define DMODEL 1024
#define NH 16
#define HD 64
#define MROWS (BATCH * SEQ)   // 4096

// Scratch (allocation-free rule: __device__ globals)
__device__ float g_Q[MROWS * DMODEL];
__device__ float g_K[MROWS * DMODEL];
__device__ float g_V[MROWS * DMODEL];
__device__ float g_C[MROWS * DMODEL];

// ---------------------------------------------------------------------------
// SGEMM: C[M,N] = A[M,K] @ W[K,N] + bias[N]
// OMODE 0: plain row-major output; OMODE 1: head-split (B,H,S,hd) output
// DSTSEL: 0 -> g_Q, 1 -> g_K, 2 -> g_V, 3 -> Cp param
// ASEL:   0 -> Ap param, 1 -> g_C
// ---------------------------------------------------------------------------
template <int OMODE, int DSTSEL, int ASEL>
__global__ __launch_bounds__(256, 2) void sgemm_kernel(
    const float* __restrict__ Ap, const float* __restrict__ W,
    const float* __restrict__ bias, float* __restrict__ Cp,
    int M, int N, int K)
{
    const float* A = (ASEL == 0) ? Ap : g_C;
    float* C = (DSTSEL == 0) ? g_Q
             : (DSTSEL == 1) ? g_K
             : (DSTSEL == 2) ? g_V
                             : Cp;

    __shared__ float As[16 * 132];  // [k][m], padded
    __shared__ float Bs[16 * 128];  // [k][n]

    const int tid = threadIdx.x;
    const int m0 = blockIdx.y * 128;
    const int n0 = blockIdx.x * 128;
    const int tx = tid & 15;
    const int ty = tid >> 4;

    float acc[8][8];
#pragma unroll
    for (int i = 0; i < 8; i++)
#pragma unroll
        for (int j = 0; j < 8; j++) acc[i][j] = 0.0f;

    const int a_row  = tid >> 2;
    const int a_col4 = (tid & 3) * 4;
    const int b_row  = tid >> 5;
    const int b_col4 = (tid & 31) * 4;

    for (int k0 = 0; k0 < K; k0 += 16) {
#pragma unroll
        for (int it = 0; it < 2; it++) {
            int r = a_row + 64 * it;
            float4 v = *reinterpret_cast<const float4*>(
                &A[(size_t)(m0 + r) * K + k0 + a_col4]);
            As[(a_col4 + 0) * 132 + r] = v.x;
            As[(a_col4 + 1) * 132 + r] = v.y;
            As[(a_col4 + 2) * 132 + r] = v.z;
            As[(a_col4 + 3) * 132 + r] = v.w;
        }
#pragma unroll
        for (int it = 0; it < 2; it++) {
            int r = b_row + 8 * it;
            *reinterpret_cast<float4*>(&Bs[r * 128 + b_col4]) =
                *reinterpret_cast<const float4*>(
                    &W[(size_t)(k0 + r) * N + n0 + b_col4]);
        }
        __syncthreads();

#pragma unroll
        for (int k = 0; k < 16; k++) {
            float ra[8], rb[8];
            *reinterpret_cast<float4*>(&ra[0]) =
                *reinterpret_cast<const float4*>(&As[k * 132 + ty * 8]);
            *reinterpret_cast<float4*>(&ra[4]) =
                *reinterpret_cast<const float4*>(&As[k * 132 + ty * 8 + 4]);
            *reinterpret_cast<float4*>(&rb[0]) =
                *reinterpret_cast<const float4*>(&Bs[k * 128 + tx * 8]);
            *reinterpret_cast<float4*>(&rb[4]) =
                *reinterpret_cast<const float4*>(&Bs[k * 128 + tx * 8 + 4]);
#pragma unroll
            for (int i = 0; i < 8; i++)
#pragma unroll
                for (int j = 0; j < 8; j++) acc[i][j] += ra[i] * rb[j];
        }
        __syncthreads();
    }

#pragma unroll
    for (int i = 0; i < 8; i++) {
        const int row = m0 + ty * 8 + i;
#pragma unroll
        for (int j = 0; j < 8; j++) {
            const int col = n0 + tx * 8 + j;
            const float v = acc[i][j] + bias[col];
            if (OMODE == 0) {
                C[(size_t)row * N + col] = v;
            } else {
                const int b = row >> 11;
                const int s = row & (SEQ - 1);
                const int h = col >> 6;
                const int d = col & (HD - 1);
                C[((size_t)(b * NH + h) * SEQ + s) * HD + d] = v;
            }
        }
    }
}

// ---------------------------------------------------------------------------
// Flash attention (causal + key padding mask), fp32.
// 256 threads; 64 queries/block; 32 keys per inner tile.
// Thread t: row r = t>>2, lane-group c = t&3.
// grid = (SEQ/64, BATCH*NH)
// ---------------------------------------------------------------------------
__global__ __launch_bounds__(256) void flash_kernel(const int* __restrict__ mask)
{
    __shared__ float Qs[64 * 68];
    __shared__ float Ks[32 * 68];
    __shared__ float Vs[32 * 68];
    __shared__ float Ps[64 * 36];

    const int tid = threadIdx.x;
    const int bh = blockIdx.y;
    const int b = bh >> 4;
    const int h = bh & 15;
    const int q0 = blockIdx.x * 64;
    const float scale = 0.125f;  // 1/sqrt(64)

    const size_t base = (size_t)bh * SEQ * HD;
    const float* Qb = g_Q + base;
    const float* Kb = g_K + base;
    const float* Vb = g_V + base;
    const int* mb = mask + b * SEQ;

    const int r = tid >> 2;
    const int c = tid & 3;

    // Load Q tile (pre-scaled)
    {
        const float* src = Qb + (size_t)(q0 + r) * HD + c * 16;
        float* dst = Qs + r * 68 + c * 16;
#pragma unroll
        for (int i = 0; i < 4; i++) {
            float4 v = *reinterpret_cast<const float4*>(src + 4 * i);
            v.x *= scale; v.y *= scale; v.z *= scale; v.w *= scale;
            *reinterpret_cast<float4*>(dst + 4 * i) = v;
        }
    }

    float o[16];
#pragma unroll
    for (int i = 0; i < 16; i++) o[i] = 0.0f;
    float mrow = -1e30f;
    float lrow = 0.0f;

    const int kr = tid >> 3;
    const int kc = (tid & 7) * 8;
    const int qq = q0 + r;
    const int ntiles = (q0 + 64) / 32;

    for (int kt = 0; kt < ntiles; kt++) {
        __syncthreads();
        {
            const float* ksrc = Kb + (size_t)(kt * 32 + kr) * HD + kc;
            const float* vsrc = Vb + (size_t)(kt * 32 + kr) * HD + kc;
            *reinterpret_cast<float4*>(Ks + kr * 68 + kc) =
                *reinterpret_cast<const float4*>(ksrc);
            *reinterpret_cast<float4*>(Ks + kr * 68 + kc + 4) =
                *reinterpret_cast<const float4*>(ksrc + 4);
            *reinterpret_cast<float4*>(Vs + kr * 68 + kc) =
                *reinterpret_cast<const float4*>(vsrc);
            *reinterpret_cast<float4*>(Vs + kr * 68 + kc + 4) =
                *reinterpret_cast<const float4*>(vsrc + 4);
        }
        __syncthreads();

        float s[8];
#pragma unroll
        for (int jj = 0; jj < 8; jj++) s[jj] = 0.0f;
#pragma unroll
        for (int k4 = 0; k4 < 16; k4++) {
            const float4 q4 =
                *reinterpret_cast<const float4*>(Qs + r * 68 + k4 * 4);
#pragma unroll
            for (int jj = 0; jj < 8; jj++) {
                const int j = jj * 4 + c;
                const float4 kv =
                    *reinterpret_cast<const float4*>(Ks + j * 68 + k4 * 4);
                s[jj] += q4.x * kv.x + q4.y * kv.y + q4.z * kv.z + q4.w * kv.w;
            }
        }
#pragma unroll
        for (int jj = 0; jj < 8; jj++) {
            const int kk = kt * 32 + jj * 4 + c;
            if (kk > qq || mb[kk] == 0) s[jj] = -1e30f;
        }

        float mt = s[0];
#pragma unroll
        for (int jj = 1; jj < 8; jj++) mt = fmaxf(mt, s[jj]);
        mt = fmaxf(mt, __shfl_xor_sync(0xffffffffu, mt, 1));
        mt = fmaxf(mt, __shfl_xor_sync(0xffffffffu, mt, 2));
        const float mnew = fmaxf(mrow, mt);
        const float alpha = __expf(mrow - mnew);

        float psum = 0.0f;
#pragma unroll
        for (int jj = 0; jj < 8; jj++) {
            const float p = __expf(s[jj] - mnew);
            psum += p;
            Ps[r * 36 + jj * 4 + c] = p;
        }
        psum += __shfl_xor_sync(0xffffffffu, psum, 1);
        psum += __shfl_xor_sync(0xffffffffu, psum, 2);
        lrow = lrow * alpha + psum;
        mrow = mnew;
#pragma unroll
        for (int i = 0; i < 16; i++) o[i] *= alpha;

        __syncthreads();

#pragma unroll 8
        for (int j = 0; j < 32; j++) {
            const float p = Ps[r * 36 + j];
            const float* vr = Vs + j * 68 + c * 16;
            const float4 v0 = *reinterpret_cast<const float4*>(vr);
            const float4 v1 = *reinterpret_cast<const float4*>(vr + 4);
            const float4 v2 = *reinterpret_cast<const float4*>(vr + 8);
            const float4 v3 = *reinterpret_cast<const float4*>(vr + 12);
            o[0]  += p * v0.x; o[1]  += p * v0.y; o[2]  += p * v0.z; o[3]  += p * v0.w;
            o[4]  += p * v1.x; o[5]  += p * v1.y; o[6]  += p * v1.z; o[7]  += p * v1.w;
            o[8]  += p * v2.x; o[9]  += p * v2.y; o[10] += p * v2.z; o[11] += p * v2.w;
            o[12] += p * v3.x; o[13] += p * v3.y; o[14] += p * v3.z; o[15] += p * v3.w;
        }
    }

    const float inv = (lrow > 0.0f) ? (1.0f / lrow) : 0.0f;
    float* dst = g_C + ((size_t)(b * SEQ + q0 + r)) * DMODEL + h * HD + c * 16;
#pragma unroll
    for (int i = 0; i < 4; i++) {
        float4 v;
        v.x = o[4 * i + 0] * inv;
        v.y = o[4 * i + 1] * inv;
        v.z = o[4 * i + 2] * inv;
        v.w = o[4 * i + 3] * inv;
        *reinterpret_cast<float4*>(dst + 4 * i) = v;
    }
}

// ---------------------------------------------------------------------------
extern "C" void kernel_launch(void* const* d_in, const int* in_sizes, int n_in,
                              void* d_out, int out_size)
{
    const float* x     = (const float*)d_in[0];
    const int*   amask = (const int*)  d_in[1];
    const float* Wq    = (const float*)d_in[2];
    const float* bq    = (const float*)d_in[3];
    const float* Wk    = (const float*)d_in[4];
    const float* bk    = (const float*)d_in[5];
    const float* Wv    = (const float*)d_in[6];
    const float* bv    = (const float*)d_in[7];
    const float* Wo    = (const float*)d_in[8];
    const float* bo    = (const float*)d_in[9];
    float* out = (float*)d_out;

    const dim3 gemm_grid(DMODEL / 128, MROWS / 128);  // (8, 32)
    const dim3 gemm_block(256);

    sgemm_kernel<1, 0, 0><<<gemm_grid, gemm_block>>>(x, Wq, bq, nullptr,
                                                     MROWS, DMODEL, DMODEL);
    sgemm_kernel<1, 1, 0><<<gemm_grid, gemm_block>>>(x, Wk, bk, nullptr,
                                                     MROWS, DMODEL, DMODEL);
    sgemm_kernel<1, 2, 0><<<gemm_grid, gemm_block>>>(x, Wv, bv, nullptr,
                                                     MROWS, DMODEL, DMODEL);

    const dim3 fa_grid(SEQ / 64, BATCH * NH);  // (32, 32)
    flash_kernel<<<fa_grid, 256>>>(amask);

    sgemm_kernel<0, 3, 1><<<gemm_grid, gemm_block>>>(nullptr, Wo, bo, out,
                                                     MROWS, DMODEL, DMODEL);
}

// round 2
// speedup vs baseline: 4.7384x; 4.7384x over previous
#include <cuda_runtime.h>

#define BATCH 2
#define SEQ 2048
#define DMODEL 1024
#define NH 16
#define HD 64
#define MROWS (BATCH * SEQ)   // 4096

// Scratch (allocation-free rule: __device__ globals)
__device__ float g_Q[MROWS * DMODEL];
__device__ float g_K[MROWS * DMODEL];
__device__ float g_V[MROWS * DMODEL];
__device__ float g_C[MROWS * DMODEL];

// ---------------------------------------------------------------------------
// helpers
// ---------------------------------------------------------------------------
__device__ __forceinline__ unsigned f2t(float f) {
    unsigned u;
    asm("cvt.rna.tf32.f32 %0, %1;" : "=r"(u) : "f"(f));
    return u;
}

__device__ __forceinline__ void mma_tf32(float* c, const unsigned* a,
                                         unsigned b0, unsigned b1) {
    asm volatile(
        "mma.sync.aligned.m16n8k8.row.col.f32.tf32.tf32.f32 "
        "{%0,%1,%2,%3}, {%4,%5,%6,%7}, {%8,%9}, {%0,%1,%2,%3};"
        : "+f"(c[0]), "+f"(c[1]), "+f"(c[2]), "+f"(c[3])
        : "r"(a[0]), "r"(a[1]), "r"(a[2]), "r"(a[3]), "r"(b0), "r"(b1));
}

// ---------------------------------------------------------------------------
// TF32 tensor-core GEMM: C[M,N] = A[M,K] @ W[K,N] + bias
// BM=128 BN=128 BK=32, 256 threads (8 warps as 2m x 4n), warp tile 64x32.
// OMODE 0: row-major out; 1: head-split (B,H,S,hd). DSTSEL/ASEL as before.
// ---------------------------------------------------------------------------
template <int OMODE, int DSTSEL, int ASEL>
__global__ __launch_bounds__(256) void gemm_tf32(
    const float* __restrict__ Ap, const float* __restrict__ W,
    const float* __restrict__ bias, float* __restrict__ Cp,
    int M, int N, int K)
{
    const float* A = (ASEL == 0) ? Ap : g_C;
    float* C = (DSTSEL == 0) ? g_Q
             : (DSTSEL == 1) ? g_K
             : (DSTSEL == 2) ? g_V
                             : Cp;

    __shared__ float As[32 * 132];  // [k][m] tf32 bits, padded
    __shared__ float Bs[32 * 132];  // [k][n] tf32 bits, padded

    const int tid = threadIdx.x;
    const int lane = tid & 31;
    const int warp = tid >> 5;
    const int g = lane >> 2;       // group id (0..7)
    const int tg = lane & 3;       // thread in group (0..3)
    const int m0 = blockIdx.y * 128;
    const int n0 = blockIdx.x * 128;
    const int wm = (warp >> 2) * 64;  // warp m offset (0/64)
    const int wn = (warp & 3) * 32;   // warp n offset

    float acc[4][4][4];
#pragma unroll
    for (int mi = 0; mi < 4; mi++)
#pragma unroll
        for (int ni = 0; ni < 4; ni++)
#pragma unroll
            for (int q = 0; q < 4; q++) acc[mi][ni][q] = 0.0f;

    for (int k0 = 0; k0 < K; k0 += 32) {
        // load + cvt tiles (1024 float4 each; 4 per thread)
#pragma unroll
        for (int i = 0; i < 4; i++) {
            const int t4 = tid + 256 * i;
            {   // A: 128 rows x 32 cols -> As[k][m]
                const int r = t4 >> 3;
                const int c4 = (t4 & 7) * 4;
                float4 v = *reinterpret_cast<const float4*>(
                    &A[(size_t)(m0 + r) * K + k0 + c4]);
                As[(c4 + 0) * 132 + r] = __uint_as_float(f2t(v.x));
                As[(c4 + 1) * 132 + r] = __uint_as_float(f2t(v.y));
                As[(c4 + 2) * 132 + r] = __uint_as_float(f2t(v.z));
                As[(c4 + 3) * 132 + r] = __uint_as_float(f2t(v.w));
            }
            {   // B: 32 rows x 128 cols -> Bs[k][n]
                const int r = t4 >> 5;
                const int c4 = (t4 & 31) * 4;
                float4 v = *reinterpret_cast<const float4*>(
                    &W[(size_t)(k0 + r) * N + n0 + c4]);
                float4 t;
                t.x = __uint_as_float(f2t(v.x));
                t.y = __uint_as_float(f2t(v.y));
                t.z = __uint_as_float(f2t(v.z));
                t.w = __uint_as_float(f2t(v.w));
                *reinterpret_cast<float4*>(&Bs[r * 132 + c4]) = t;
            }
        }
        __syncthreads();

#pragma unroll
        for (int ks = 0; ks < 4; ks++) {
            const int kb = ks * 8;
            unsigned a[4][4], b[4][2];
#pragma unroll
            for (int mi = 0; mi < 4; mi++) {
                const int mrow = wm + mi * 16 + g;
                a[mi][0] = __float_as_uint(As[(kb + tg) * 132 + mrow]);
                a[mi][1] = __float_as_uint(As[(kb + tg) * 132 + mrow + 8]);
                a[mi][2] = __float_as_uint(As[(kb + tg + 4) * 132 + mrow]);
                a[mi][3] = __float_as_uint(As[(kb + tg + 4) * 132 + mrow + 8]);
            }
#pragma unroll
            for (int ni = 0; ni < 4; ni++) {
                const int nc = wn + ni * 8 + g;
                b[ni][0] = __float_as_uint(Bs[(kb + tg) * 132 + nc]);
                b[ni][1] = __float_as_uint(Bs[(kb + tg + 4) * 132 + nc]);
            }
#pragma unroll
            for (int mi = 0; mi < 4; mi++)
#pragma unroll
                for (int ni = 0; ni < 4; ni++)
                    mma_tf32(acc[mi][ni], a[mi], b[ni][0], b[ni][1]);
        }
        __syncthreads();
    }

    // epilogue
#pragma unroll
    for (int mi = 0; mi < 4; mi++) {
#pragma unroll
        for (int ni = 0; ni < 4; ni++) {
            const int row0 = m0 + wm + mi * 16 + g;
            const int row1 = row0 + 8;
            const int col = n0 + wn + ni * 8 + 2 * tg;
            const float b0 = bias[col];
            const float b1 = bias[col + 1];
            float2 v0 = make_float2(acc[mi][ni][0] + b0, acc[mi][ni][1] + b1);
            float2 v1 = make_float2(acc[mi][ni][2] + b0, acc[mi][ni][3] + b1);
            if (OMODE == 0) {
                *reinterpret_cast<float2*>(&C[(size_t)row0 * N + col]) = v0;
                *reinterpret_cast<float2*>(&C[(size_t)row1 * N + col]) = v1;
            } else {
                const int h = col >> 6;
                const int d = col & (HD - 1);
                {
                    const int b = row0 >> 11, s = row0 & (SEQ - 1);
                    *reinterpret_cast<float2*>(
                        &C[((size_t)(b * NH + h) * SEQ + s) * HD + d]) = v0;
                }
                {
                    const int b = row1 >> 11, s = row1 & (SEQ - 1);
                    *reinterpret_cast<float2*>(
                        &C[((size_t)(b * NH + h) * SEQ + s) * HD + d]) = v1;
                }
            }
        }
    }
}

// ---------------------------------------------------------------------------
// TF32 tensor-core flash attention (causal + key padding mask).
// 128 threads (4 warps); 64 queries/block; 64-key tiles.
// Warp w owns query rows [w*16, w*16+16). Q frags register-resident.
// P routed through the (dead after init) Q smem buffer.
// grid = (SEQ/64, BATCH*NH)
// ---------------------------------------------------------------------------
#define FP 68  // smem pitch (floats)

__global__ __launch_bounds__(128) void flash_tf32(const int* __restrict__ mask)
{
    extern __shared__ float smem[];
    float* QP = smem;                 // 64 x FP : Q, then reused for P
    float* Ks = smem + 64 * FP;       // 64 x FP
    float* Vs = smem + 2 * 64 * FP;   // 64 x FP
    int*  s_msk  = reinterpret_cast<int*>(smem + 3 * 64 * FP);      // 64
    unsigned* s_ball = reinterpret_cast<unsigned*>(s_msk + 64);     // 2

    const int tid = threadIdx.x;
    const int lane = tid & 31;
    const int warp = tid >> 5;
    const int g = lane >> 2;
    const int tg = lane & 3;
    const int wm = warp * 16;

    const int bh = blockIdx.y;
    const int b = bh >> 4;
    const int h = bh & 15;
    const int q0 = blockIdx.x * 64;
    const size_t base = (size_t)bh * SEQ * HD;
    const int* mb = mask + b * SEQ;

    // --- load Q tile (scaled, tf32) ---
#pragma unroll
    for (int i = 0; i < 8; i++) {
        const int t4 = tid + 128 * i;
        const int r = t4 >> 4;
        const int c4 = (t4 & 15) * 4;
        float4 v = *reinterpret_cast<const float4*>(
            &g_Q[base + (size_t)(q0 + r) * HD + c4]);
        float4 t;
        t.x = __uint_as_float(f2t(v.x * 0.125f));
        t.y = __uint_as_float(f2t(v.y * 0.125f));
        t.z = __uint_as_float(f2t(v.z * 0.125f));
        t.w = __uint_as_float(f2t(v.w * 0.125f));
        *reinterpret_cast<float4*>(&QP[r * FP + c4]) = t;
    }
    __syncthreads();

    // --- Q fragments into registers (8 k-steps x 4 regs) ---
    unsigned qf[8][4];
#pragma unroll
    for (int ks = 0; ks < 8; ks++) {
        const int kb = ks * 8;
        qf[ks][0] = __float_as_uint(QP[(wm + g) * FP + kb + tg]);
        qf[ks][1] = __float_as_uint(QP[(wm + g + 8) * FP + kb + tg]);
        qf[ks][2] = __float_as_uint(QP[(wm + g) * FP + kb + tg + 4]);
        qf[ks][3] = __float_as_uint(QP[(wm + g + 8) * FP + kb + tg + 4]);
    }

    float o[8][4];
#pragma unroll
    for (int nt = 0; nt < 8; nt++)
#pragma unroll
        for (int q = 0; q < 4; q++) o[nt][q] = 0.0f;
    float m0r = -1e30f, m1r = -1e30f, l0 = 0.0f, l1 = 0.0f;

    const int qr0 = q0 + wm + g;
    const int qr1 = qr0 + 8;
    const int ntiles = blockIdx.x + 1;

    for (int kt = 0; kt < ntiles; kt++) {
        const int k0 = kt * 64;
        __syncthreads();
        // load K/V tile (tf32) + mask
#pragma unroll
        for (int i = 0; i < 8; i++) {
            const int t4 = tid + 128 * i;
            const int r = t4 >> 4;
            const int c4 = (t4 & 15) * 4;
            float4 kv = *reinterpret_cast<const float4*>(
                &g_K[base + (size_t)(k0 + r) * HD + c4]);
            float4 vv = *reinterpret_cast<const float4*>(
                &g_V[base + (size_t)(k0 + r) * HD + c4]);
            float4 tk, tv;
            tk.x = __uint_as_float(f2t(kv.x)); tk.y = __uint_as_float(f2t(kv.y));
            tk.z = __uint_as_float(f2t(kv.z)); tk.w = __uint_as_float(f2t(kv.w));
            tv.x = __uint_as_float(f2t(vv.x)); tv.y = __uint_as_float(f2t(vv.y));
            tv.z = __uint_as_float(f2t(vv.z)); tv.w = __uint_as_float(f2t(vv.w));
            *reinterpret_cast<float4*>(&Ks[r * FP + c4]) = tk;
            *reinterpret_cast<float4*>(&Vs[r * FP + c4]) = tv;
        }
        if (warp < 2) {
            const int mv = mb[k0 + tid];
            if (tid < 64) s_msk[tid] = mv;
            unsigned bl = __ballot_sync(0xffffffffu, mv != 0);
            if (lane == 0) s_ball[warp] = bl;
        }
        __syncthreads();

        const bool need_pad = (s_ball[0] & s_ball[1]) != 0xffffffffu;
        const bool diag = (kt == blockIdx.x);

        // --- scores S = Q K^T (per warp: 16 x 64) ---
        float S[8][4];
#pragma unroll
        for (int nt = 0; nt < 8; nt++)
#pragma unroll
            for (int q = 0; q < 4; q++) S[nt][q] = 0.0f;
#pragma unroll
        for (int ks = 0; ks < 8; ks++) {
            const int kb = ks * 8;
#pragma unroll
            for (int nt = 0; nt < 8; nt++) {
                const unsigned b0 =
                    __float_as_uint(Ks[(nt * 8 + g) * FP + kb + tg]);
                const unsigned b1 =
                    __float_as_uint(Ks[(nt * 8 + g) * FP + kb + tg + 4]);
                mma_tf32(S[nt], qf[ks], b0, b1);
            }
        }

        // --- masking ---
        if (diag || need_pad) {
#pragma unroll
            for (int nt = 0; nt < 8; nt++) {
                const int kk0 = k0 + nt * 8 + 2 * tg;
#pragma unroll
                for (int j = 0; j < 2; j++) {
                    const int kk = kk0 + j;
                    const bool pad = need_pad && (s_msk[kk - k0] == 0);
                    if ((diag && kk > qr0) || pad) S[nt][j] = -1e30f;
                    if ((diag && kk > qr1) || pad) S[nt][2 + j] = -1e30f;
                }
            }
        }

        // --- online softmax (rows g and g+8) ---
        float mt0 = -1e30f, mt1 = -1e30f;
#pragma unroll
        for (int nt = 0; nt < 8; nt++) {
            mt0 = fmaxf(mt0, fmaxf(S[nt][0], S[nt][1]));
            mt1 = fmaxf(mt1, fmaxf(S[nt][2], S[nt][3]));
        }
        mt0 = fmaxf(mt0, __shfl_xor_sync(0xffffffffu, mt0, 1));
        mt0 = fmaxf(mt0, __shfl_xor_sync(0xffffffffu, mt0, 2));
        mt1 = fmaxf(mt1, __shfl_xor_sync(0xffffffffu, mt1, 1));
        mt1 = fmaxf(mt1, __shfl_xor_sync(0xffffffffu, mt1, 2));
        const float mn0 = fmaxf(m0r, mt0);
        const float mn1 = fmaxf(m1r, mt1);
        const float a0 = __expf(m0r - mn0);
        const float a1 = __expf(m1r - mn1);

        __syncwarp();  // prior PV reads of QP done before overwriting P

        float s0 = 0.0f, s1 = 0.0f;
#pragma unroll
        for (int nt = 0; nt < 8; nt++) {
            const float p00 = __expf(S[nt][0] - mn0);
            const float p01 = __expf(S[nt][1] - mn0);
            const float p10 = __expf(S[nt][2] - mn1);
            const float p11 = __expf(S[nt][3] - mn1);
            s0 += p00 + p01;
            s1 += p10 + p11;
            const int c = nt * 8 + 2 * tg;
            float2 w0 = make_float2(__uint_as_float(f2t(p00)),
                                    __uint_as_float(f2t(p01)));
            float2 w1 = make_float2(__uint_as_float(f2t(p10)),
                                    __uint_as_float(f2t(p11)));
            *reinterpret_cast<float2*>(&QP[(wm + g) * FP + c]) = w0;
            *reinterpret_cast<float2*>(&QP[(wm + g + 8) * FP + c]) = w1;
        }
        s0 += __shfl_xor_sync(0xffffffffu, s0, 1);
        s0 += __shfl_xor_sync(0xffffffffu, s0, 2);
        s1 += __shfl_xor_sync(0xffffffffu, s1, 1);
        s1 += __shfl_xor_sync(0xffffffffu, s1, 2);
        l0 = l0 * a0 + s0;
        l1 = l1 * a1 + s1;
        m0r = mn0;
        m1r = mn1;
#pragma unroll
        for (int nt = 0; nt < 8; nt++) {
            o[nt][0] *= a0; o[nt][1] *= a0;
            o[nt][2] *= a1; o[nt][3] *= a1;
        }
        __syncwarp();  // P visible to all lanes of this warp

        // --- O += P V ---
#pragma unroll
        for (int ks = 0; ks < 8; ks++) {
            const int kb = ks * 8;
            unsigned pa[4];
            pa[0] = __float_as_uint(QP[(wm + g) * FP + kb + tg]);
            pa[1] = __float_as_uint(QP[(wm + g + 8) * FP + kb + tg]);
            pa[2] = __float_as_uint(QP[(wm + g) * FP + kb + tg + 4]);
            pa[3] = __float_as_uint(QP[(wm + g + 8) * FP + kb + tg + 4]);
#pragma unroll
            for (int nt = 0; nt < 8; nt++) {
                const unsigned b0 =
                    __float_as_uint(Vs[(kb + tg) * FP + nt * 8 + g]);
                const unsigned b1 =
                    __float_as_uint(Vs[(kb + tg + 4) * FP + nt * 8 + g]);
                mma_tf32(o[nt], pa, b0, b1);
            }
        }
    }

    // --- epilogue: ctx -> g_C (B,S,D) ---
    const float i0 = 1.0f / l0;
    const float i1 = 1.0f / l1;
#pragma unroll
    for (int nt = 0; nt < 8; nt++) {
        const int d = nt * 8 + 2 * tg;
        float* p0 = &g_C[((size_t)(b * SEQ + qr0)) * DMODEL + h * HD + d];
        float* p1 = &g_C[((size_t)(b * SEQ + qr1)) * DMODEL + h * HD + d];
        *reinterpret_cast<float2*>(p0) = make_float2(o[nt][0] * i0, o[nt][1] * i0);
        *reinterpret_cast<float2*>(p1) = make_float2(o[nt][2] * i1, o[nt][3] * i1);
    }
}

// ---------------------------------------------------------------------------
extern "C" void kernel_launch(void* const* d_in, const int* in_sizes, int n_in,
                              void* d_out, int out_size)
{
    const float* x     = (const float*)d_in[0];
    const int*   amask = (const int*)  d_in[1];
    const float* Wq    = (const float*)d_in[2];
    const float* bq    = (const float*)d_in[3];
    const float* Wk    = (const float*)d_in[4];
    const float* bk    = (const float*)d_in[5];
    const float* Wv    = (const float*)d_in[6];
    const float* bv    = (const float*)d_in[7];
    const float* Wo    = (const float*)d_in[8];
    const float* bo    = (const float*)d_in[9];
    float* out = (float*)d_out;

    const dim3 gemm_grid(DMODEL / 128, MROWS / 128);  // (8, 32)

    gemm_tf32<1, 0, 0><<<gemm_grid, 256>>>(x, Wq, bq, nullptr,
                                           MROWS, DMODEL, DMODEL);
    gemm_tf32<1, 1, 0><<<gemm_grid, 256>>>(x, Wk, bk, nullptr,
                                           MROWS, DMODEL, DMODEL);
    gemm_tf32<1, 2, 0><<<gemm_grid, 256>>>(x, Wv, bv, nullptr,
                                           MROWS, DMODEL, DMODEL);

    const int fa_smem = 3 * 64 * FP * 4 + 64 * 4 + 2 * 4 + 16;
    cudaFuncSetAttribute(flash_tf32,
                         cudaFuncAttributeMaxDynamicSharedMemorySize, fa_smem);
    const dim3 fa_grid(SEQ / 64, BATCH * NH);  // (32, 32)
    flash_tf32<<<fa_grid, 128, fa_smem>>>(amask);

    gemm_tf32<0, 3, 1><<<gemm_grid, 256>>>(nullptr, Wo, bo, out,
                                           MROWS, DMODEL, DMODEL);
}

// round 3
// speedup vs baseline: 6.8668x; 1.4492x over previous
#include <cuda_runtime.h>

#define BATCH 2
#define SEQ 2048
#define DMODEL 1024
#define NH 16
#define HD 64
#define MROWS (BATCH * SEQ)   // 4096

// Scratch (allocation-free rule: __device__ globals)
__device__ float g_Q[MROWS * DMODEL];
__device__ float g_K[MROWS * DMODEL];
__device__ float g_V[MROWS * DMODEL];
__device__ float g_C[MROWS * DMODEL];                 // x_tf32, later ctx
__device__ float g_W[4 * DMODEL * DMODEL];            // tf32 weights

// ---------------------------------------------------------------------------
// helpers
// ---------------------------------------------------------------------------
__device__ __forceinline__ unsigned f2t(float f) {
    unsigned u;
    asm("cvt.rna.tf32.f32 %0, %1;" : "=r"(u) : "f"(f));
    return u;
}
__device__ __forceinline__ float f2tf(float f) { return __uint_as_float(f2t(f)); }

__device__ __forceinline__ void mma_tf32(float* c, const unsigned* a,
                                         unsigned b0, unsigned b1) {
    asm volatile(
        "mma.sync.aligned.m16n8k8.row.col.f32.tf32.tf32.f32 "
        "{%0,%1,%2,%3}, {%4,%5,%6,%7}, {%8,%9}, {%0,%1,%2,%3};"
        : "+f"(c[0]), "+f"(c[1]), "+f"(c[2]), "+f"(c[3])
        : "r"(a[0]), "r"(a[1]), "r"(a[2]), "r"(a[3]), "r"(b0), "r"(b1));
}

__device__ __forceinline__ void cpa16(float* s, const float* g) {
    unsigned a = (unsigned)__cvta_generic_to_shared(s);
    asm volatile("cp.async.cg.shared.global [%0], [%1], 16;" :: "r"(a), "l"(g));
}
__device__ __forceinline__ void cp_commit() {
    asm volatile("cp.async.commit_group;");
}
template <int N>
__device__ __forceinline__ void cp_wait() {
    asm volatile("cp.async.wait_group %0;" :: "n"(N));
}

// ---------------------------------------------------------------------------
// Pre-convert x and all weights to tf32 bits (one RNA rounding, moved here).
// x -> g_C ; Wq,Wk,Wv,Wo -> g_W[0..3]
// ---------------------------------------------------------------------------
__global__ __launch_bounds__(256) void cvt_all(
    const float4* __restrict__ x,  const float4* __restrict__ wq,
    const float4* __restrict__ wk, const float4* __restrict__ wv,
    const float4* __restrict__ wo)
{
    const int i = blockIdx.x * 256 + threadIdx.x;  // 0 .. 2M-1 (float4)
    float4 v;
    float4* dst;
    if (i < 1048576) {                      // x: 4M floats
        v = x[i];
        dst = reinterpret_cast<float4*>(g_C) + i;
    } else {
        const int j = i - 1048576;          // weights: 4 x 256K float4
        const int w = j >> 18;
        const int off = j & 262143;
        const float4* src = (w == 0) ? wq : (w == 1) ? wk : (w == 2) ? wv : wo;
        v = src[off];
        dst = reinterpret_cast<float4*>(g_W) + j;
    }
    float4 t;
    t.x = f2tf(v.x); t.y = f2tf(v.y); t.z = f2tf(v.z); t.w = f2tf(v.w);
    *dst = t;
}

// ---------------------------------------------------------------------------
// TF32 GEMM, cp.async 2-stage double buffered. A = g_C (tf32), W from g_W.
// BM=128 BN=128 BK=32, 256 threads (8 warps 2m x 4n), warp tile 64x32.
// MODE 0: fused QKV (z = blockIdx.z), head-split tf32 output to g_Q/K/V.
// MODE 1: Wo, fp32 row-major output to outp.
// Stage layout: As 128x36 (row-major), Bs 32x136.  8960 floats/stage.
// ---------------------------------------------------------------------------
#define GS 8960  // floats per stage

template <int MODE>
__global__ __launch_bounds__(256, 2) void gemm_db(
    const float* __restrict__ b0p, const float* __restrict__ b1p,
    const float* __restrict__ b2p, float* __restrict__ outp)
{
    extern __shared__ float sm[];

    const int z = (MODE == 0) ? blockIdx.z : 3;
    const float* __restrict__ A = g_C;
    const float* __restrict__ W = g_W + (size_t)z * (DMODEL * DMODEL);
    const float* bias = (MODE == 0)
        ? ((z == 0) ? b0p : (z == 1) ? b1p : b2p) : b0p;
    float* dstQ = (z == 0) ? g_Q : (z == 1) ? g_K : g_V;

    const int tid = threadIdx.x;
    const int lane = tid & 31;
    const int warp = tid >> 5;
    const int g = lane >> 2;
    const int tg = lane & 3;
    const int m0 = blockIdx.y * 128;
    const int n0 = blockIdx.x * 128;
    const int wm = (warp >> 2) * 64;
    const int wn = (warp & 3) * 32;

    float acc[4][4][4];
#pragma unroll
    for (int mi = 0; mi < 4; mi++)
#pragma unroll
        for (int ni = 0; ni < 4; ni++)
#pragma unroll
            for (int q = 0; q < 4; q++) acc[mi][ni][q] = 0.0f;

    // cp.async tile loader: per thread 4 A-chunks + 4 B-chunks (16B each)
    auto load_tile = [&](int t, int st) {
        float* As = sm + st * GS;
        float* Bs = As + 4608;
        const int k0 = t * 32;
#pragma unroll
        for (int u = 0; u < 4; u++) {
            const int c = tid + 256 * u;          // 0..1023
            const int ar = c >> 3, ak = (c & 7) * 4;
            cpa16(As + ar * 36 + ak,
                  A + (size_t)(m0 + ar) * DMODEL + k0 + ak);
            const int br = c >> 5, bn = (c & 31) * 4;
            cpa16(Bs + br * 136 + bn,
                  W + (size_t)(k0 + br) * DMODEL + n0 + bn);
        }
    };

    load_tile(0, 0);
    cp_commit();

#pragma unroll 1
    for (int t = 0; t < 32; t++) {
        if (t < 31) {
            load_tile(t + 1, (t + 1) & 1);
            cp_commit();
            cp_wait<1>();
        } else {
            cp_wait<0>();
        }
        __syncthreads();

        const float* As = sm + (t & 1) * GS;
        const float* Bs = As + 4608;
#pragma unroll
        for (int ks = 0; ks < 4; ks++) {
            const int kb = ks * 8;
            unsigned a[4][4], b[4][2];
#pragma unroll
            for (int mi = 0; mi < 4; mi++) {
                const float* ar = As + (wm + mi * 16 + g) * 36 + kb + tg;
                a[mi][0] = __float_as_uint(ar[0]);
                a[mi][1] = __float_as_uint(ar[8 * 36]);
                a[mi][2] = __float_as_uint(ar[4]);
                a[mi][3] = __float_as_uint(ar[8 * 36 + 4]);
            }
#pragma unroll
            for (int ni = 0; ni < 4; ni++) {
                const float* br = Bs + (kb + tg) * 136 + wn + ni * 8 + g;
                b[ni][0] = __float_as_uint(br[0]);
                b[ni][1] = __float_as_uint(br[4 * 136]);
            }
#pragma unroll
            for (int mi = 0; mi < 4; mi++)
#pragma unroll
                for (int ni = 0; ni < 4; ni++)
                    mma_tf32(acc[mi][ni], a[mi], b[ni][0], b[ni][1]);
        }
        __syncthreads();
    }

    // epilogue
#pragma unroll
    for (int mi = 0; mi < 4; mi++) {
#pragma unroll
        for (int ni = 0; ni < 4; ni++) {
            const int row0 = m0 + wm + mi * 16 + g;
            const int row1 = row0 + 8;
            const int col = n0 + wn + ni * 8 + 2 * tg;
            const float bb0 = bias[col];
            const float bb1 = bias[col + 1];
            if (MODE == 1) {
                float2 v0 = make_float2(acc[mi][ni][0] + bb0,
                                        acc[mi][ni][1] + bb1);
                float2 v1 = make_float2(acc[mi][ni][2] + bb0,
                                        acc[mi][ni][3] + bb1);
                *reinterpret_cast<float2*>(&outp[(size_t)row0 * DMODEL + col]) = v0;
                *reinterpret_cast<float2*>(&outp[(size_t)row1 * DMODEL + col]) = v1;
            } else {
                // head-split (B,H,S,hd), tf32-rounded for downstream mma
                float2 v0 = make_float2(f2tf(acc[mi][ni][0] + bb0),
                                        f2tf(acc[mi][ni][1] + bb1));
                float2 v1 = make_float2(f2tf(acc[mi][ni][2] + bb0),
                                        f2tf(acc[mi][ni][3] + bb1));
                const int h = col >> 6;
                const int d = col & (HD - 1);
                {
                    const int b = row0 >> 11, s = row0 & (SEQ - 1);
                    *reinterpret_cast<float2*>(
                        &dstQ[((size_t)(b * NH + h) * SEQ + s) * HD + d]) = v0;
                }
                {
                    const int b = row1 >> 11, s = row1 & (SEQ - 1);
                    *reinterpret_cast<float2*>(
                        &dstQ[((size_t)(b * NH + h) * SEQ + s) * HD + d]) = v1;
                }
            }
        }
    }
}

// ---------------------------------------------------------------------------
// TF32 flash attention (causal + key padding). 128 threads (4 warps),
// 64 queries/block, 64-key tiles. Inputs already tf32-rounded.
// Heavy-first block order for triangular load balance.
// Ks pitch 68 (score reads conflict-free), Vs pitch 72 (PV reads conflict-free)
// grid = (SEQ/64, BATCH*NH)
// ---------------------------------------------------------------------------
#define FQ 68   // QP / Ks pitch
#define FV 72   // Vs pitch
#define SM_QP 0
#define SM_KS (64 * FQ)
#define SM_VS (SM_KS + 64 * FQ)
#define SM_END (SM_VS + 64 * FV)

__global__ __launch_bounds__(128) void flash_tf32(const int* __restrict__ mask)
{
    extern __shared__ float smem[];
    float* QP = smem + SM_QP;
    float* Ks = smem + SM_KS;
    float* Vs = smem + SM_VS;
    int*  s_msk  = reinterpret_cast<int*>(smem + SM_END);
    unsigned* s_ball = reinterpret_cast<unsigned*>(s_msk + 64);

    const int tid = threadIdx.x;
    const int lane = tid & 31;
    const int warp = tid >> 5;
    const int g = lane >> 2;
    const int tg = lane & 3;
    const int wm = warp * 16;

    const int bh = blockIdx.y;
    const int b = bh >> 4;
    const int h = bh & 15;
    const int qt = gridDim.x - 1 - blockIdx.x;   // heavy-first
    const int q0 = qt * 64;
    const size_t base = (size_t)bh * SEQ * HD;
    const int* mb = mask + b * SEQ;

    // --- load Q tile (x 0.125 exact power-of-two: stays tf32) ---
#pragma unroll
    for (int i = 0; i < 8; i++) {
        const int t4 = tid + 128 * i;
        const int r = t4 >> 4;
        const int c4 = (t4 & 15) * 4;
        float4 v = *reinterpret_cast<const float4*>(
            &g_Q[base + (size_t)(q0 + r) * HD + c4]);
        v.x *= 0.125f; v.y *= 0.125f; v.z *= 0.125f; v.w *= 0.125f;
        *reinterpret_cast<float4*>(&QP[r * FQ + c4]) = v;
    }
    __syncthreads();

    // --- Q fragments into registers ---
    unsigned qf[8][4];
#pragma unroll
    for (int ks = 0; ks < 8; ks++) {
        const int kb = ks * 8;
        qf[ks][0] = __float_as_uint(QP[(wm + g) * FQ + kb + tg]);
        qf[ks][1] = __float_as_uint(QP[(wm + g + 8) * FQ + kb + tg]);
        qf[ks][2] = __float_as_uint(QP[(wm + g) * FQ + kb + tg + 4]);
        qf[ks][3] = __float_as_uint(QP[(wm + g + 8) * FQ + kb + tg + 4]);
    }

    float o[8][4];
#pragma unroll
    for (int nt = 0; nt < 8; nt++)
#pragma unroll
        for (int q = 0; q < 4; q++) o[nt][q] = 0.0f;
    float m0r = -1e30f, m1r = -1e30f, l0 = 0.0f, l1 = 0.0f;

    const int qr0 = q0 + wm + g;
    const int qr1 = qr0 + 8;
    const int ntiles = qt + 1;

    for (int kt = 0; kt < ntiles; kt++) {
        const int k0 = kt * 64;
        __syncthreads();
        // K/V fill via cp.async (no cvt needed; already tf32)
#pragma unroll
        for (int u = 0; u < 8; u++) {
            const int c = tid + 128 * u;       // 0..1023
            const int r = c >> 4;
            const int c4 = (c & 15) * 4;
            cpa16(Ks + r * FQ + c4, &g_K[base + (size_t)(k0 + r) * HD + c4]);
            cpa16(Vs + r * FV + c4, &g_V[base + (size_t)(k0 + r) * HD + c4]);
        }
        cp_commit();
        if (warp < 2) {
            const int mv = mb[k0 + tid];
            if (tid < 64) s_msk[tid] = mv;
            unsigned bl = __ballot_sync(0xffffffffu, mv != 0);
            if (lane == 0) s_ball[warp] = bl;
        }
        cp_wait<0>();
        __syncthreads();

        const bool need_pad = (s_ball[0] & s_ball[1]) != 0xffffffffu;
        const bool diag = (kt == qt);

        // --- scores S = Q K^T ---
        float S[8][4];
#pragma unroll
        for (int nt = 0; nt < 8; nt++)
#pragma unroll
            for (int q = 0; q < 4; q++) S[nt][q] = 0.0f;
#pragma unroll
        for (int ks = 0; ks < 8; ks++) {
            const int kb = ks * 8;
#pragma unroll
            for (int nt = 0; nt < 8; nt++) {
                const unsigned b0 =
                    __float_as_uint(Ks[(nt * 8 + g) * FQ + kb + tg]);
                const unsigned b1 =
                    __float_as_uint(Ks[(nt * 8 + g) * FQ + kb + tg + 4]);
                mma_tf32(S[nt], qf[ks], b0, b1);
            }
        }

        // --- masking ---
        if (diag || need_pad) {
#pragma unroll
            for (int nt = 0; nt < 8; nt++) {
                const int kk0 = k0 + nt * 8 + 2 * tg;
#pragma unroll
                for (int j = 0; j < 2; j++) {
                    const int kk = kk0 + j;
                    const bool pad = need_pad && (s_msk[kk - k0] == 0);
                    if ((diag && kk > qr0) || pad) S[nt][j] = -1e30f;
                    if ((diag && kk > qr1) || pad) S[nt][2 + j] = -1e30f;
                }
            }
        }

        // --- online softmax ---
        float mt0 = -1e30f, mt1 = -1e30f;
#pragma unroll
        for (int nt = 0; nt < 8; nt++) {
            mt0 = fmaxf(mt0, fmaxf(S[nt][0], S[nt][1]));
            mt1 = fmaxf(mt1, fmaxf(S[nt][2], S[nt][3]));
        }
        mt0 = fmaxf(mt0, __shfl_xor_sync(0xffffffffu, mt0, 1));
        mt0 = fmaxf(mt0, __shfl_xor_sync(0xffffffffu, mt0, 2));
        mt1 = fmaxf(mt1, __shfl_xor_sync(0xffffffffu, mt1, 1));
        mt1 = fmaxf(mt1, __shfl_xor_sync(0xffffffffu, mt1, 2));
        const float mn0 = fmaxf(m0r, mt0);
        const float mn1 = fmaxf(m1r, mt1);
        const float a0 = __expf(m0r - mn0);
        const float a1 = __expf(m1r - mn1);

        __syncwarp();  // prior PV reads of QP done before overwriting P

        float s0 = 0.0f, s1 = 0.0f;
#pragma unroll
        for (int nt = 0; nt < 8; nt++) {
            const float p00 = __expf(S[nt][0] - mn0);
            const float p01 = __expf(S[nt][1] - mn0);
            const float p10 = __expf(S[nt][2] - mn1);
            const float p11 = __expf(S[nt][3] - mn1);
            s0 += p00 + p01;
            s1 += p10 + p11;
            const int c = nt * 8 + 2 * tg;
            *reinterpret_cast<float2*>(&QP[(wm + g) * FQ + c]) =
                make_float2(f2tf(p00), f2tf(p01));
            *reinterpret_cast<float2*>(&QP[(wm + g + 8) * FQ + c]) =
                make_float2(f2tf(p10), f2tf(p11));
        }
        s0 += __shfl_xor_sync(0xffffffffu, s0, 1);
        s0 += __shfl_xor_sync(0xffffffffu, s0, 2);
        s1 += __shfl_xor_sync(0xffffffffu, s1, 1);
        s1 += __shfl_xor_sync(0xffffffffu, s1, 2);
        l0 = l0 * a0 + s0;
        l1 = l1 * a1 + s1;
        m0r = mn0;
        m1r = mn1;
#pragma unroll
        for (int nt = 0; nt < 8; nt++) {
            o[nt][0] *= a0; o[nt][1] *= a0;
            o[nt][2] *= a1; o[nt][3] *= a1;
        }
        __syncwarp();  // P visible to all lanes of this warp

        // --- O += P V ---
#pragma unroll
        for (int ks = 0; ks < 8; ks++) {
            const int kb = ks * 8;
            unsigned pa[4];
            pa[0] = __float_as_uint(QP[(wm + g) * FQ + kb + tg]);
            pa[1] = __float_as_uint(QP[(wm + g + 8) * FQ + kb + tg]);
            pa[2] = __float_as_uint(QP[(wm + g) * FQ + kb + tg + 4]);
            pa[3] = __float_as_uint(QP[(wm + g + 8) * FQ + kb + tg + 4]);
#pragma unroll
            for (int nt = 0; nt < 8; nt++) {
                const unsigned b0 =
                    __float_as_uint(Vs[(kb + tg) * FV + nt * 8 + g]);
                const unsigned b1 =
                    __float_as_uint(Vs[(kb + tg + 4) * FV + nt * 8 + g]);
                mma_tf32(o[nt], pa, b0, b1);
            }
        }
    }

    // --- epilogue: ctx -> g_C (B,S,D), tf32-rounded for Wo GEMM ---
    const float i0 = 1.0f / l0;
    const float i1 = 1.0f / l1;
#pragma unroll
    for (int nt = 0; nt < 8; nt++) {
        const int d = nt * 8 + 2 * tg;
        float* p0 = &g_C[((size_t)(b * SEQ + qr0)) * DMODEL + h * HD + d];
        float* p1 = &g_C[((size_t)(b * SEQ + qr1)) * DMODEL + h * HD + d];
        *reinterpret_cast<float2*>(p0) =
            make_float2(f2tf(o[nt][0] * i0), f2tf(o[nt][1] * i0));
        *reinterpret_cast<float2*>(p1) =
            make_float2(f2tf(o[nt][2] * i1), f2tf(o[nt][3] * i1));
    }
}

// ---------------------------------------------------------------------------
extern "C" void kernel_launch(void* const* d_in, const int* in_sizes, int n_in,
                              void* d_out, int out_size)
{
    const float* x     = (const float*)d_in[0];
    const int*   amask = (const int*)  d_in[1];
    const float* Wq    = (const float*)d_in[2];
    const float* bq    = (const float*)d_in[3];
    const float* Wk    = (const float*)d_in[4];
    const float* bk    = (const float*)d_in[5];
    const float* Wv    = (const float*)d_in[6];
    const float* bv    = (const float*)d_in[7];
    const float* Wo    = (const float*)d_in[8];
    const float* bo    = (const float*)d_in[9];
    float* out = (float*)d_out;

    // 1. pre-convert x + weights to tf32
    cvt_all<<<8192, 256>>>(
        (const float4*)x, (const float4*)Wq, (const float4*)Wk,
        (const float4*)Wv, (const float4*)Wo);

    const int gemm_smem = 2 * GS * 4;  // 71680 B
    cudaFuncSetAttribute(gemm_db<0>,
                         cudaFuncAttributeMaxDynamicSharedMemorySize, gemm_smem);
    cudaFuncSetAttribute(gemm_db<1>,
                         cudaFuncAttributeMaxDynamicSharedMemorySize, gemm_smem);

    // 2. fused QKV projection
    gemm_db<0><<<dim3(DMODEL / 128, MROWS / 128, 3), 256, gemm_smem>>>(
        bq, bk, bv, nullptr);

    // 3. flash attention
    const int fa_smem = SM_END * 4 + 64 * 4 + 2 * 4 + 8;
    cudaFuncSetAttribute(flash_tf32,
                         cudaFuncAttributeMaxDynamicSharedMemorySize, fa_smem);
    flash_tf32<<<dim3(SEQ / 64, BATCH * NH), 128, fa_smem>>>(amask);

    // 4. output projection
    gemm_db<1><<<dim3(DMODEL / 128, MROWS / 128, 1), 256, gemm_smem>>>(
        bo, nullptr, nullptr, out);
}